// round 5
// baseline (speedup 1.0000x reference)
#include <cuda_runtime.h>
#include <cuda_bf16.h>
#include <cuda_fp16.h>
#include <cstdint>

#define N_ROWS 16384
#define DIM    1024
#define BM     128
#define BN     128
#define BK     64
#define STAGES 3
#define NTHREADS 256
#define A_STAGE_BYTES (BM * BK * 2)                    /* 16384 */
#define B_STAGE_BYTES (BN * BK * 2)                    /* 16384 */
#define STAGE_BYTES   (A_STAGE_BYTES + B_STAGE_BYTES)  /* 32768 */
#define SMEM_DYN      (STAGES * STAGE_BYTES)           /* 96 KB */

// __device__ scratch (allowed; no runtime allocation)
__device__ __nv_bfloat16 g_A[(size_t)N_ROWS * DIM];  // norm image * s*log2e
__device__ __nv_bfloat16 g_B[(size_t)N_ROWS * DIM];  // normalized text
__device__ double g_sum;

// ---------------------------------------------------------------------------
// Kernel 1: L2-normalize rows (fp32) -> bf16. Image rows additionally scaled
// by s*log2(e) so the GEMM directly yields the exp2 argument (minus bias).
// ---------------------------------------------------------------------------
__global__ __launch_bounds__(256) void normalize_kernel(
    const float* __restrict__ img, const float* __restrict__ txt,
    const float* __restrict__ lsp)
{
    int b = blockIdx.x;
    if (b == 0 && threadIdx.x == 0) g_sum = 0.0;
    bool is_img = (b < N_ROWS);
    int r = is_img ? b : b - N_ROWS;
    const float4* src = reinterpret_cast<const float4*>(
        (is_img ? img : txt) + (size_t)r * DIM);
    float4 v = src[threadIdx.x];
    float ss = v.x * v.x + v.y * v.y + v.z * v.z + v.w * v.w;
#pragma unroll
    for (int o = 16; o; o >>= 1) ss += __shfl_xor_sync(0xffffffffu, ss, o);
    __shared__ float wss[8];
    if ((threadIdx.x & 31) == 0) wss[threadIdx.x >> 5] = ss;
    __syncthreads();
    float tot = 0.f;
#pragma unroll
    for (int i = 0; i < 8; i++) tot += wss[i];
    float inv = rsqrtf(tot);
    if (is_img) inv *= __expf(lsp[0]) * 1.4426950408889634f;  // s*log2e

    __nv_bfloat162 lo, hi;
    lo.x = __float2bfloat16_rn(v.x * inv);
    lo.y = __float2bfloat16_rn(v.y * inv);
    hi.x = __float2bfloat16_rn(v.z * inv);
    hi.y = __float2bfloat16_rn(v.w * inv);
    uint32_t ulo = *reinterpret_cast<uint32_t*>(&lo);
    uint32_t uhi = *reinterpret_cast<uint32_t*>(&hi);
    uint64_t pk = ((uint64_t)uhi << 32) | (uint64_t)ulo;
    __nv_bfloat16* dst = is_img ? g_A : g_B;
    reinterpret_cast<uint64_t*>(dst + (size_t)r * DIM)[threadIdx.x] = pk;
}

// ---------------------------------------------------------------------------
// Kernel 2: fused GEMM (bf16 mma.sync, fp32 acc) + packed-f16x2 exp epilogue.
// 128x128 tile, BK=64, 3-stage cp.async pipeline, 2 CTAs/SM.
// Fragments double-buffered across the 4 k16 steps so LDSM overlaps HMMA.
// acc = s*log2e*dot, so term = 2^acc * e^bias; diag adds -(acc*ln2 + bias).
// ---------------------------------------------------------------------------
__device__ __forceinline__ uint32_t smoff(int row, int ch)
{
    return (uint32_t)(row * 128 + ((ch ^ (row & 7)) << 4));
}

__global__ __launch_bounds__(NTHREADS, 2) void siglip_gemm_kernel(
    const float* __restrict__ lbp)
{
    extern __shared__ __align__(128) uint8_t smem[];

    const int tid  = threadIdx.x;
    const int lane = tid & 31;
    const int wid  = tid >> 5;
    const int wm   = (wid & 1) * 64;   // warp M offset in tile
    const int wn   = (wid >> 1) * 32;  // warp N offset in tile
    const int bm   = blockIdx.y;
    const int bn   = blockIdx.x;

    uint32_t smemA = (uint32_t)__cvta_generic_to_shared(smem);
    uint32_t smemB = smemA + STAGES * A_STAGE_BYTES;

    const __nv_bfloat16* gA = g_A + (size_t)bm * BM * DIM;
    const __nv_bfloat16* gB = g_B + (size_t)bn * BN * DIM;

    float acc[4][4][4];
#pragma unroll
    for (int i = 0; i < 4; i++)
#pragma unroll
        for (int j = 0; j < 4; j++)
#pragma unroll
            for (int r = 0; r < 4; r++) acc[i][j][r] = 0.f;

    auto load_stage = [&](int st, int kt) {
#pragma unroll
        for (int i = 0; i < 4; i++) {  // A: 1024 16B chunks (128 rows x 8)
            int cid = tid + i * 256;
            int row = cid >> 3, ch = cid & 7;
            const void* s = gA + (size_t)row * DIM + kt * BK + ch * 8;
            uint32_t d = smemA + st * A_STAGE_BYTES + smoff(row, ch);
            asm volatile("cp.async.cg.shared.global [%0], [%1], 16;\n" ::"r"(d), "l"(s));
        }
#pragma unroll
        for (int i = 0; i < 4; i++) {  // B: 1024 16B chunks
            int cid = tid + i * 256;
            int row = cid >> 3, ch = cid & 7;
            const void* s = gB + (size_t)row * DIM + kt * BK + ch * 8;
            uint32_t d = smemB + st * B_STAGE_BYTES + smoff(row, ch);
            asm volatile("cp.async.cg.shared.global [%0], [%1], 16;\n" ::"r"(d), "l"(s));
        }
    };

    // frag loaders (per k16 step)
    const int arow = wm + ((lane >> 3) & 1) * 8 + (lane & 7);
    const int achb = (lane >> 4);
    const int brow = wn + (lane >> 3) * 8 + (lane & 7);

    auto load_a = [&](uint32_t aBase, int kk, uint32_t (&a)[4][4]) {
        int ch = kk * 2 + achb;
#pragma unroll
        for (int i = 0; i < 4; i++) {
            uint32_t addr = aBase + smoff(arow + i * 16, ch);
            asm volatile(
                "ldmatrix.sync.aligned.m8n8.x4.shared.b16 {%0,%1,%2,%3}, [%4];\n"
                : "=r"(a[i][0]), "=r"(a[i][1]), "=r"(a[i][2]), "=r"(a[i][3])
                : "r"(addr));
        }
    };
    auto load_b = [&](uint32_t bBase, int kk, uint32_t (&b)[8]) {
        int c0 = kk * 2;
        uint32_t addr0 = bBase + smoff(brow, c0);
        uint32_t addr1 = bBase + smoff(brow, c0 + 1);
        asm volatile(
            "ldmatrix.sync.aligned.m8n8.x4.shared.b16 {%0,%1,%2,%3}, [%4];\n"
            : "=r"(b[0]), "=r"(b[1]), "=r"(b[2]), "=r"(b[3]) : "r"(addr0));
        asm volatile(
            "ldmatrix.sync.aligned.m8n8.x4.shared.b16 {%0,%1,%2,%3}, [%4];\n"
            : "=r"(b[4]), "=r"(b[5]), "=r"(b[6]), "=r"(b[7]) : "r"(addr1));
    };

    // prologue: stages 0..STAGES-2
#pragma unroll
    for (int s = 0; s < STAGES - 1; ++s) {
        load_stage(s, s);
        asm volatile("cp.async.commit_group;\n" ::);
    }

    uint32_t afrag[2][4][4];
    uint32_t bfrag[2][8];

    const int KT = DIM / BK;  // 16
    for (int kt = 0; kt < KT; ++kt) {
        asm volatile("cp.async.wait_group %0;\n" ::"n"(STAGES - 2));
        __syncthreads();

        // issue next global loads first so they overlap the MMA phase
        int nk = kt + STAGES - 1;
        if (nk < KT) load_stage(nk % STAGES, nk);
        asm volatile("cp.async.commit_group;\n" ::);

        int st = kt % STAGES;
        uint32_t aBase = smemA + st * A_STAGE_BYTES;
        uint32_t bBase = smemB + st * B_STAGE_BYTES;

        load_a(aBase, 0, afrag[0]);
        load_b(bBase, 0, bfrag[0]);

#pragma unroll
        for (int kk = 0; kk < 4; ++kk) {
            int cur = kk & 1, nxt = cur ^ 1;
            if (kk < 3) {
                load_a(aBase, kk + 1, afrag[nxt]);
                load_b(bBase, kk + 1, bfrag[nxt]);
            }
#pragma unroll
            for (int i = 0; i < 4; i++)
#pragma unroll
                for (int j = 0; j < 4; j++) {
                    asm volatile(
                        "mma.sync.aligned.m16n8k16.row.col.f32.bf16.bf16.f32 "
                        "{%0,%1,%2,%3}, {%4,%5,%6,%7}, {%8,%9}, {%0,%1,%2,%3};\n"
                        : "+f"(acc[i][j][0]), "+f"(acc[i][j][1]),
                          "+f"(acc[i][j][2]), "+f"(acc[i][j][3])
                        : "r"(afrag[cur][i][0]), "r"(afrag[cur][i][1]),
                          "r"(afrag[cur][i][2]), "r"(afrag[cur][i][3]),
                          "r"(bfrag[cur][j]), "r"(bfrag[cur][4 + j]));
                }
        }
    }

    // -------- fused epilogue: 2^acc via ex2.f16x2, diagonal correction -----
    float bias = lbp[0];
    float esum = 0.f;   // sum of 2^acc  (term = 2^acc * e^bias off-diagonal)
    float dsum = 0.f;   // diagonal -l corrections

#pragma unroll
    for (int i = 0; i < 4; i++) {
        __half2 hacc = __float2half2_rn(0.f);
#pragma unroll
        for (int j = 0; j < 4; j++) {
            uint32_t p0, p1, e0, e1;
            asm("cvt.rn.f16x2.f32 %0, %1, %2;" : "=r"(p0)
                : "f"(acc[i][j][1]), "f"(acc[i][j][0]));
            asm("cvt.rn.f16x2.f32 %0, %1, %2;" : "=r"(p1)
                : "f"(acc[i][j][3]), "f"(acc[i][j][2]));
            asm("ex2.approx.f16x2 %0, %1;" : "=r"(e0) : "r"(p0));
            asm("ex2.approx.f16x2 %0, %1;" : "=r"(e1) : "r"(p1));
            __half2 h0 = *reinterpret_cast<__half2*>(&e0);
            __half2 h1 = *reinterpret_cast<__half2*>(&e1);
            hacc = __hadd2(hacc, __hadd2(h0, h1));
        }
        float2 f2 = __half22float2(hacc);
        esum += f2.x + f2.y;
    }

    if (bm == bn) {  // diagonal tile: add -l; l = acc*ln2 + bias
        const float LN2 = 0.6931471805599453f;
        int rb = wm + (lane >> 2);
        int cb = wn + ((lane & 3) << 1);
#pragma unroll
        for (int i = 0; i < 4; i++)
#pragma unroll
            for (int j = 0; j < 4; j++)
#pragma unroll
                for (int r = 0; r < 4; r++) {
                    int rg = rb + i * 16 + ((r >> 1) << 3);
                    int cg = cb + j * 8 + (r & 1);
                    if (rg == cg)
                        dsum -= fmaf(acc[i][j][r], LN2, bias);
                }
    }

    float tsum = fmaf(esum, __expf(bias), dsum);
#pragma unroll
    for (int o = 16; o; o >>= 1) tsum += __shfl_xor_sync(0xffffffffu, tsum, o);

    asm volatile("cp.async.wait_group 0;\n" ::);
    __syncthreads();  // smem tiles no longer needed; reuse for reduction
    float* wsum = reinterpret_cast<float*>(smem);
    if (lane == 0) wsum[wid] = tsum;
    __syncthreads();
    if (tid == 0) {
        float bs = 0.f;
#pragma unroll
        for (int i = 0; i < 8; i++) bs += wsum[i];
        atomicAdd(&g_sum, (double)bs);
    }
}

// ---------------------------------------------------------------------------
// Kernel 3: finalize scalar
// ---------------------------------------------------------------------------
__global__ void finalize_kernel(float* out)
{
    out[0] = (float)(g_sum * (1.0 / ((double)N_ROWS * (double)N_ROWS)));
}

extern "C" void kernel_launch(void* const* d_in, const int* in_sizes, int n_in,
                              void* d_out, int out_size)
{
    const float* img = (const float*)d_in[0];
    const float* txt = (const float*)d_in[1];
    const float* ls  = (const float*)d_in[2];
    const float* lb  = (const float*)d_in[3];

    normalize_kernel<<<2 * N_ROWS, 256>>>(img, txt, ls);

    cudaFuncSetAttribute(siglip_gemm_kernel,
                         cudaFuncAttributeMaxDynamicSharedMemorySize, SMEM_DYN);
    dim3 grid(N_ROWS / BN, N_ROWS / BM);
    siglip_gemm_kernel<<<grid, NTHREADS, SMEM_DYN>>>(lb);

    finalize_kernel<<<1, 1>>>((float*)d_out);
}